// round 15
// baseline (speedup 1.0000x reference)
#include <cuda_runtime.h>
#include <cuda_fp16.h>
#include <cstdint>

#define NN 100000
#define EE 1600000
#define DD 128
#define NB 98            // ceil(NN/1024)

// ---------------- scratch (device globals: no allocation allowed) ----------------
__device__ int    g_counts[NN];
__device__ int    g_offsets[NN];
__device__ int    g_bsums[128];
__device__ int    g_rank[EE];         // edge's rank within its dst bucket (from hist)
__device__ int    g_csr_src[EE];
__device__ __half g_xh[(size_t)NN * DD];    // fp16 input features
__device__ __half g_hh[(size_t)NN * DD];    // fp16 layer-1 activations
// preconverted fp16 weights: [layer][256 k][128 n] (k 0-127 = Wself, 128-255 = Wneigh)
__device__ __half g_wh[2 * 256 * DD];

// ---------------- CSR build ----------------
// hist (records intra-bucket rank -> atomic-free scatter) + fused x->fp16 convert
#define HB ((EE + 255) / 256)
__global__ void hist_fused_kernel(const int* __restrict__ dst, const float* __restrict__ x) {
    if (blockIdx.x < HB) {
        int i = blockIdx.x * 256 + threadIdx.x;
        if (i < EE) g_rank[i] = atomicAdd(&g_counts[dst[i]], 1);
    } else {
        int i = (blockIdx.x - HB) * 256 + threadIdx.x;   // float4 index
        if (i < NN * DD / 4) {
            float4 v = __ldg(reinterpret_cast<const float4*>(x) + i);
            __half2 h0 = __floats2half2_rn(v.x, v.y);
            __half2 h1 = __floats2half2_rn(v.z, v.w);
            reinterpret_cast<uint2*>(g_xh)[i] = make_uint2(*(uint32_t*)&h0, *(uint32_t*)&h1);
        }
    }
}

__global__ void scan_local_kernel() {
    __shared__ int wsums[32];
    int tid = threadIdx.x, lane = tid & 31, warp = tid >> 5;
    int i = blockIdx.x * 1024 + tid;
    int v = (i < NN) ? g_counts[i] : 0;
    int x = v;
    #pragma unroll
    for (int o = 1; o < 32; o <<= 1) {
        int t = __shfl_up_sync(0xffffffffu, x, o);
        if (lane >= o) x += t;
    }
    if (lane == 31) wsums[warp] = x;
    __syncthreads();
    if (warp == 0) {
        int w = wsums[lane];
        #pragma unroll
        for (int o = 1; o < 32; o <<= 1) {
            int t = __shfl_up_sync(0xffffffffu, w, o);
            if (lane >= o) w += t;
        }
        wsums[lane] = w;
    }
    __syncthreads();
    int incl = x + (warp ? wsums[warp - 1] : 0);
    if (i < NN) g_offsets[i] = incl - v;               // block-local exclusive
    if (tid == 1023) g_bsums[blockIdx.x] = incl;       // block total
}

// finalize with fused block-sums scan
__global__ void finalize_kernel() {
    __shared__ int pref[NB];
    int tid = threadIdx.x;
    if (tid < NB) pref[tid] = g_bsums[tid];
    __syncthreads();
    if (tid == 0) {
        int run = 0;
        #pragma unroll 7
        for (int j = 0; j < NB; ++j) { int t = pref[j]; pref[j] = run; run += t; }
    }
    __syncthreads();
    int i = blockIdx.x * blockDim.x + tid;
    if (i < NN) g_offsets[i] += pref[i >> 10];
}

// atomic-free scatter + fused W fp16 preconversion (extra 64 blocks)
#define SC_BLOCKS ((EE + 255) / 256)
__global__ void scatter_fused_kernel(const int* __restrict__ src, const int* __restrict__ dst,
                                     const float* __restrict__ W1s, const float* __restrict__ W1n,
                                     const float* __restrict__ W2s, const float* __restrict__ W2n) {
    if (blockIdx.x < SC_BLOCKS) {
        int i = blockIdx.x * 256 + threadIdx.x;
        if (i < EE) {
            int d = dst[i];
            int p = __ldg(&g_offsets[d]) + g_rank[i];
            g_csr_src[p] = src[i];
        }
    } else {
        int i = (blockIdx.x - SC_BLOCKS) * 256 + threadIdx.x;
        if (i >= 16384) return;
        int layer = i >> 13;
        int r256  = (i >> 5) & 255;
        int c4    = i & 31;
        const float* Wsrc = (layer == 0)
            ? ((r256 < 128) ? W1s + (size_t)r256 * DD : W1n + (size_t)(r256 - 128) * DD)
            : ((r256 < 128) ? W2s + (size_t)r256 * DD : W2n + (size_t)(r256 - 128) * DD);
        float4 v = *reinterpret_cast<const float4*>(Wsrc + c4 * 4);
        __half2 h0 = __floats2half2_rn(v.x, v.y);
        __half2 h1 = __floats2half2_rn(v.z, v.w);
        reinterpret_cast<uint2*>(g_wh)[i] = make_uint2(*(uint32_t*)&h0, *(uint32_t*)&h1);
    }
}

// ====== FUSED agg + fp16 GEMM ======
// Block = 128 nodes. Phase 1: 8 warps aggregate 16 nodes each (frozen gather loop)
// into smem mean tiles (fp16, A-tile layout, K-chunks 4-7). Phase 2: pipelined GEMM;
// chunks 0-3 read self features via double-buffered gmem copies, chunks 4-7
// ldmatrix directly from the mean tiles.
__device__ __forceinline__ uint32_t smem_u32(const void* p) {
    uint32_t a;
    asm("{ .reg .u64 t; cvta.to.shared.u64 t, %1; cvt.u32.u64 %0, t; }" : "=r"(a) : "l"(p));
    return a;
}
__device__ __forceinline__ void ldsm_x4(uint32_t& r0, uint32_t& r1, uint32_t& r2, uint32_t& r3, uint32_t a) {
    asm volatile("ldmatrix.sync.aligned.m8n8.x4.shared.b16 {%0,%1,%2,%3}, [%4];"
                 : "=r"(r0), "=r"(r1), "=r"(r2), "=r"(r3) : "r"(a));
}
__device__ __forceinline__ void ldsm_x4_t(uint32_t& r0, uint32_t& r1, uint32_t& r2, uint32_t& r3, uint32_t a) {
    asm volatile("ldmatrix.sync.aligned.m8n8.x4.trans.shared.b16 {%0,%1,%2,%3}, [%4];"
                 : "=r"(r0), "=r"(r1), "=r"(r2), "=r"(r3) : "r"(a));
}
__device__ __forceinline__ void mma_fp16(float* c, uint32_t a0, uint32_t a1, uint32_t a2, uint32_t a3,
                                         uint32_t b0, uint32_t b1) {
    asm volatile("mma.sync.aligned.m16n8k16.row.col.f32.f16.f16.f32 "
                 "{%0,%1,%2,%3}, {%4,%5,%6,%7}, {%8,%9}, {%0,%1,%2,%3};"
                 : "+f"(c[0]), "+f"(c[1]), "+f"(c[2]), "+f"(c[3])
                 : "r"(a0), "r"(a1), "r"(a2), "r"(a3), "r"(b0), "r"(b1));
}
__device__ __forceinline__ uint32_t pack_h2(float x, float y) {
    __half2 t = __floats2half2_rn(x, y);
    return *reinterpret_cast<uint32_t*>(&t);
}

#define APAD 40
#define BPAD 136
#define MEANTILE 10240       // 128 rows * APAD halves * 2B
#define PIPE_OFF 40960       // 4 mean tiles
#define OFF_A 0
#define OFF_B 10240
#define BUFSZ 18944          // OFF_B + 32*BPAD*2
#define GSMEM (PIPE_OFF + 2 * BUFSZ)   // 78848

// mode 1: relu, write fp16 to outh. mode 0: write fp32 to outf.
__global__ __launch_bounds__(256, 2) void fused_gemm_kernel(
    const __half* __restrict__ X,    // [NN][128] fp16 features (self + gather source)
    const __half* __restrict__ Wh,   // [256 k][128 n] fp16
    const float* __restrict__ bias,
    float* __restrict__ outf, __half* __restrict__ outh, int mode)
{
    extern __shared__ char smem[];
    int tid = threadIdx.x, lane = tid & 31, wid = tid >> 5;
    int warp_m = wid & 3;
    int warp_n = wid >> 2;
    int m0 = blockIdx.x * 128;
    uint32_t sb = smem_u32(smem);

    // ---- phase 1: gather/mean into smem tiles (each warp: 16 nodes) ----
    {
        const uint2* xr = reinterpret_cast<const uint2*>(X);
        int mchunk = lane >> 3;              // 0..3: which K-chunk tile
        int cic    = (lane * 4) & 31;        // half-col within chunk
        for (int j = 0; j < 16; ++j) {
            int nl = wid * 16 + j;
            int gm = m0 + nl;
            float a0 = 0.f, a1 = 0.f, a2 = 0.f, a3 = 0.f;
            if (gm < NN) {
                int s   = g_offsets[gm];
                int cnt = g_counts[gm];
                int t = 0;
                for (; t + 8 <= cnt; t += 8) {
                    int idx[8];
                    #pragma unroll
                    for (int u = 0; u < 8; ++u) idx[u] = __ldg(&g_csr_src[s + t + u]);
                    uint2 v[8];
                    #pragma unroll
                    for (int u = 0; u < 8; ++u)
                        v[u] = __ldg(&xr[(size_t)idx[u] * 32 + lane]);
                    #pragma unroll
                    for (int u = 0; u < 8; ++u) {
                        float2 f0 = __half22float2(*reinterpret_cast<__half2*>(&v[u].x));
                        float2 f1 = __half22float2(*reinterpret_cast<__half2*>(&v[u].y));
                        a0 += f0.x; a1 += f0.y; a2 += f1.x; a3 += f1.y;
                    }
                }
                for (; t < cnt; ++t) {
                    int i0 = __ldg(&g_csr_src[s + t]);
                    uint2 v = __ldg(&xr[(size_t)i0 * 32 + lane]);
                    float2 f0 = __half22float2(*reinterpret_cast<__half2*>(&v.x));
                    float2 f1 = __half22float2(*reinterpret_cast<__half2*>(&v.y));
                    a0 += f0.x; a1 += f0.y; a2 += f1.x; a3 += f1.y;
                }
                float di = 1.0f / (float)((cnt > 1) ? cnt : 1);
                a0 *= di; a1 *= di; a2 *= di; a3 *= di;
            }
            uint2 o = make_uint2(pack_h2(a0, a1), pack_h2(a2, a3));
            *reinterpret_cast<uint2*>(smem + mchunk * MEANTILE + (uint32_t)(nl * APAD + cic) * 2) = o;
        }
    }

    float acc[2][8][4];
    #pragma unroll
    for (int i = 0; i < 2; ++i)
        #pragma unroll
        for (int j = 0; j < 8; ++j)
            #pragma unroll
            for (int q = 0; q < 4; ++q) acc[i][j][q] = 0.f;

    int a_lrow = lane & 15;
    int a_lcol = (lane >> 4) << 3;
    int b_lk   = lane & 15;
    int b_ln   = (lane >> 4) << 3;

    // ---- prologue: copy self chunk 0 + W chunk 0 into pipe buffer 0 ----
    {
        char* base = smem + PIPE_OFF;
        #pragma unroll
        for (int i = 0; i < 4; ++i) {
            int f = tid + i * 256;
            int row = f >> 3, c4 = (f & 7) * 4;
            int gm = m0 + row;
            uint2 v = (gm < NN) ? __ldg(reinterpret_cast<const uint2*>(X + (size_t)gm * DD + c4))
                                : make_uint2(0u, 0u);
            *reinterpret_cast<uint2*>(base + OFF_A + (uint32_t)(row * APAD + c4) * 2) = v;
        }
        #pragma unroll
        for (int i = 0; i < 2; ++i) {
            int u = tid + i * 256;
            int kr = u >> 4, n8 = (u & 15) * 8;
            uint4 v = __ldg(reinterpret_cast<const uint4*>(Wh + (size_t)kr * DD + n8));
            *reinterpret_cast<uint4*>(base + OFF_B + (uint32_t)(kr * BPAD + n8) * 2) = v;
        }
    }
    __syncthreads();

    for (int ch = 0; ch < 8; ++ch) {
        // ---- prefetch next self chunk's A (only chunks 1-3 come from gmem) ----
        uint2 av2[4];
        if (ch < 3) {
            int cb = (ch + 1) * 32;
            #pragma unroll
            for (int i = 0; i < 4; ++i) {
                int f = tid + i * 256;
                int row = f >> 3, c4 = (f & 7) * 4;
                int gm = m0 + row;
                av2[i] = (gm < NN) ? __ldg(reinterpret_cast<const uint2*>(X + (size_t)gm * DD + cb + c4))
                                   : make_uint2(0u, 0u);
            }
        }

        // ---- compute ----
        uint32_t a_b = (ch < 4)
            ? (sb + PIPE_OFF + (uint32_t)(ch & 1) * BUFSZ + OFF_A)
            : (sb + (uint32_t)(ch - 4) * MEANTILE);
        uint32_t b_b = sb + PIPE_OFF + (uint32_t)(ch & 1) * BUFSZ + OFF_B;

        #pragma unroll
        for (int ks = 0; ks < 2; ++ks) {
            uint32_t a[2][4];
            #pragma unroll
            for (int mt = 0; mt < 2; ++mt) {
                int row = warp_m * 32 + mt * 16 + a_lrow;
                int col = ks * 16 + a_lcol;
                ldsm_x4(a[mt][0], a[mt][1], a[mt][2], a[mt][3],
                        a_b + (uint32_t)(row * APAD + col) * 2);
            }
            #pragma unroll
            for (int ng = 0; ng < 4; ++ng) {
                int kk = ks * 16 + b_lk;
                int nn = warp_n * 64 + ng * 16 + b_ln;
                uint32_t b0, b1, b2, b3;
                ldsm_x4_t(b0, b1, b2, b3, b_b + (uint32_t)(kk * BPAD + nn) * 2);
                #pragma unroll
                for (int mt = 0; mt < 2; ++mt) {
                    mma_fp16(acc[mt][ng * 2 + 0], a[mt][0], a[mt][1], a[mt][2], a[mt][3], b0, b1);
                    mma_fp16(acc[mt][ng * 2 + 1], a[mt][0], a[mt][1], a[mt][2], a[mt][3], b2, b3);
                }
            }
        }

        // ---- store next chunk into other pipe buffer ----
        if (ch < 7) {
            char* base = smem + PIPE_OFF + ((ch + 1) & 1) * BUFSZ;
            if (ch < 3) {
                #pragma unroll
                for (int i = 0; i < 4; ++i) {
                    int f = tid + i * 256;
                    int row = f >> 3, c4 = (f & 7) * 4;
                    *reinterpret_cast<uint2*>(base + OFF_A + (uint32_t)(row * APAD + c4) * 2) = av2[i];
                }
            }
            #pragma unroll
            for (int i = 0; i < 2; ++i) {
                int u = tid + i * 256;
                int kr = u >> 4, n8 = (u & 15) * 8;
                uint4 v = __ldg(reinterpret_cast<const uint4*>(Wh + (size_t)((ch + 1) * 32 + kr) * DD + n8));
                *reinterpret_cast<uint4*>(base + OFF_B + (uint32_t)(kr * BPAD + n8) * 2) = v;
            }
            __syncthreads();
        }
    }

    // --- epilogue ---
    int crow = lane >> 2;
    int ccol = (lane & 3) * 2;
    #pragma unroll
    for (int mt = 0; mt < 2; ++mt) {
        #pragma unroll
        for (int nt = 0; nt < 8; ++nt) {
            int col = warp_n * 64 + nt * 8 + ccol;
            float2 bb = __ldg(reinterpret_cast<const float2*>(bias + col));
            #pragma unroll
            for (int h = 0; h < 2; ++h) {
                int row = m0 + warp_m * 32 + mt * 16 + crow + h * 8;
                if (row >= NN) continue;
                float lo = acc[mt][nt][h * 2 + 0] + bb.x;
                float hi = acc[mt][nt][h * 2 + 1] + bb.y;
                if (mode == 1) {
                    lo = fmaxf(lo, 0.f); hi = fmaxf(hi, 0.f);
                    *reinterpret_cast<uint32_t*>(outh + (size_t)row * DD + col) = pack_h2(lo, hi);
                } else {
                    *reinterpret_cast<float2*>(outf + (size_t)row * DD + col) = make_float2(lo, hi);
                }
            }
        }
    }
}

// ---------------- launch ----------------
extern "C" void kernel_launch(void* const* d_in, const int* in_sizes, int n_in,
                              void* d_out, int out_size) {
    const float* in_feat  = (const float*)d_in[0];
    const float* W1_self  = (const float*)d_in[1];
    const float* W1_neigh = (const float*)d_in[2];
    const float* b1       = (const float*)d_in[3];
    const float* W2_self  = (const float*)d_in[4];
    const float* W2_neigh = (const float*)d_in[5];
    const float* b2       = (const float*)d_in[6];
    const int*   src      = (const int*)d_in[7];
    const int*   dst      = (const int*)d_in[8];
    float* out = (float*)d_out;

    int* counts_p;
    __half *xh_p, *hh_p, *wh_p;
    cudaGetSymbolAddress((void**)&counts_p, g_counts);
    cudaGetSymbolAddress((void**)&xh_p, g_xh);
    cudaGetSymbolAddress((void**)&hh_p, g_hh);
    cudaGetSymbolAddress((void**)&wh_p, g_wh);

    cudaFuncSetAttribute(fused_gemm_kernel, cudaFuncAttributeMaxDynamicSharedMemorySize, GSMEM);

    cudaMemsetAsync(counts_p, 0, NN * sizeof(int));

    int conv_blocks = (NN * DD / 4 + 255) / 256;
    hist_fused_kernel<<<HB + conv_blocks, 256>>>(dst, in_feat);
    scan_local_kernel<<<NB, 1024>>>();
    finalize_kernel<<<(NN + 255) / 256, 256>>>();
    scatter_fused_kernel<<<SC_BLOCKS + 64, 256>>>(src, dst,
        W1_self, W1_neigh, W2_self, W2_neigh);

    int gemm_grid = (NN + 127) / 128;

    // layer 1 (fused agg + GEMM, fp16 h out)
    fused_gemm_kernel<<<gemm_grid, 256, GSMEM>>>(xh_p, wh_p, b1, nullptr, hh_p, 1);
    // layer 2 (fused agg + GEMM, fp32 out)
    fused_gemm_kernel<<<gemm_grid, 256, GSMEM>>>(hh_p, wh_p + 256 * DD, b2, out, nullptr, 0);
}

// round 17
// speedup vs baseline: 1.3262x; 1.3262x over previous
#include <cuda_runtime.h>
#include <cuda_fp16.h>
#include <cstdint>

#define NN 100000
#define EE 1600000
#define DD 128
#define NB 98            // ceil(NN/1024)

// ---------------- scratch (device globals: no allocation allowed) ----------------
__device__ int    g_counts[NN];
__device__ int    g_offsets[NN];
__device__ float  g_deginv[NN];
__device__ int    g_bsums[128];
__device__ int    g_rank[EE];         // edge's rank within its dst bucket (from hist)
__device__ int    g_csr_src[EE];
__device__ __half g_xh[(size_t)NN * DD];    // fp16 input features
__device__ __half g_mh[(size_t)NN * DD];    // fp16 neighbor means
__device__ __half g_hh[(size_t)NN * DD];    // fp16 layer-1 activations
// preconverted fp16 weights: [layer][256 k][128 n] (k 0-127 = Wself, 128-255 = Wneigh)
__device__ __half g_wh[2 * 256 * DD];

// ---------------- CSR build ----------------
// hist (records intra-bucket rank -> atomic-free scatter) + fused x->fp16 convert
#define HB ((EE + 255) / 256)
__global__ void hist_fused_kernel(const int* __restrict__ dst, const float* __restrict__ x) {
    if (blockIdx.x < HB) {
        int i = blockIdx.x * 256 + threadIdx.x;
        if (i < EE) g_rank[i] = atomicAdd(&g_counts[dst[i]], 1);
    } else {
        int i = (blockIdx.x - HB) * 256 + threadIdx.x;   // float4 index
        if (i < NN * DD / 4) {
            float4 v = __ldg(reinterpret_cast<const float4*>(x) + i);
            __half2 h0 = __floats2half2_rn(v.x, v.y);
            __half2 h1 = __floats2half2_rn(v.z, v.w);
            reinterpret_cast<uint2*>(g_xh)[i] = make_uint2(*(uint32_t*)&h0, *(uint32_t*)&h1);
        }
    }
}

__global__ void scan_local_kernel() {
    __shared__ int wsums[32];
    int tid = threadIdx.x, lane = tid & 31, warp = tid >> 5;
    int i = blockIdx.x * 1024 + tid;
    int v = (i < NN) ? g_counts[i] : 0;
    int x = v;
    #pragma unroll
    for (int o = 1; o < 32; o <<= 1) {
        int t = __shfl_up_sync(0xffffffffu, x, o);
        if (lane >= o) x += t;
    }
    if (lane == 31) wsums[warp] = x;
    __syncthreads();
    if (warp == 0) {
        int w = wsums[lane];
        #pragma unroll
        for (int o = 1; o < 32; o <<= 1) {
            int t = __shfl_up_sync(0xffffffffu, w, o);
            if (lane >= o) w += t;
        }
        wsums[lane] = w;
    }
    __syncthreads();
    int incl = x + (warp ? wsums[warp - 1] : 0);
    if (i < NN) g_offsets[i] = incl - v;               // block-local exclusive
    if (tid == 1023) g_bsums[blockIdx.x] = incl;       // block total
}

// finalize with fused block-sums scan
__global__ void finalize_kernel() {
    __shared__ int pref[NB];
    int tid = threadIdx.x;
    if (tid < NB) pref[tid] = g_bsums[tid];
    __syncthreads();
    if (tid == 0) {
        int run = 0;
        #pragma unroll 7
        for (int j = 0; j < NB; ++j) { int t = pref[j]; pref[j] = run; run += t; }
    }
    __syncthreads();
    int i = blockIdx.x * blockDim.x + tid;
    if (i < NN) {
        int off = g_offsets[i] + pref[i >> 10];
        g_offsets[i] = off;
        int c = g_counts[i];
        g_deginv[i]  = 1.0f / (float)((c > 1) ? c : 1);
    }
}

// atomic-free scatter + fused W fp16 preconversion (extra 64 blocks)
#define SC_BLOCKS ((EE + 255) / 256)
__global__ void scatter_fused_kernel(const int* __restrict__ src, const int* __restrict__ dst,
                                     const float* __restrict__ W1s, const float* __restrict__ W1n,
                                     const float* __restrict__ W2s, const float* __restrict__ W2n) {
    if (blockIdx.x < SC_BLOCKS) {
        int i = blockIdx.x * 256 + threadIdx.x;
        if (i < EE) {
            int d = dst[i];
            int p = __ldg(&g_offsets[d]) + g_rank[i];
            g_csr_src[p] = src[i];
        }
    } else {
        int i = (blockIdx.x - SC_BLOCKS) * 256 + threadIdx.x;
        if (i >= 16384) return;
        int layer = i >> 13;
        int r256  = (i >> 5) & 255;
        int c4    = i & 31;
        const float* Wsrc = (layer == 0)
            ? ((r256 < 128) ? W1s + (size_t)r256 * DD : W1n + (size_t)(r256 - 128) * DD)
            : ((r256 < 128) ? W2s + (size_t)r256 * DD : W2n + (size_t)(r256 - 128) * DD);
        float4 v = *reinterpret_cast<const float4*>(Wsrc + c4 * 4);
        __half2 h0 = __floats2half2_rn(v.x, v.y);
        __half2 h1 = __floats2half2_rn(v.z, v.w);
        reinterpret_cast<uint2*>(g_wh)[i] = make_uint2(*(uint32_t*)&h0, *(uint32_t*)&h1);
    }
}

// -------- mean aggregation: warp per node, edge-unroll x8 (FROZEN form),
// fp16 gather (uint2/lane), fp32 accumulate, fp16 mean out --------
__global__ void agg_kernel(const __half* __restrict__ x, __half* __restrict__ outmean) {
    int node = (blockIdx.x * blockDim.x + threadIdx.x) >> 5;
    int lane = threadIdx.x & 31;
    if (node >= NN) return;
    int s   = g_offsets[node];
    int cnt = g_counts[node];
    const uint2* xr = reinterpret_cast<const uint2*>(x);
    float a0 = 0.f, a1 = 0.f, a2 = 0.f, a3 = 0.f;
    int t = 0;
    for (; t + 8 <= cnt; t += 8) {
        int idx[8];
        #pragma unroll
        for (int u = 0; u < 8; ++u) idx[u] = __ldg(&g_csr_src[s + t + u]);
        uint2 v[8];
        #pragma unroll
        for (int u = 0; u < 8; ++u)
            v[u] = __ldg(&xr[(size_t)idx[u] * 32 + lane]);
        #pragma unroll
        for (int u = 0; u < 8; ++u) {
            float2 f0 = __half22float2(*reinterpret_cast<__half2*>(&v[u].x));
            float2 f1 = __half22float2(*reinterpret_cast<__half2*>(&v[u].y));
            a0 += f0.x; a1 += f0.y; a2 += f1.x; a3 += f1.y;
        }
    }
    for (; t < cnt; ++t) {
        int i0 = __ldg(&g_csr_src[s + t]);
        uint2 v = __ldg(&xr[(size_t)i0 * 32 + lane]);
        float2 f0 = __half22float2(*reinterpret_cast<__half2*>(&v.x));
        float2 f1 = __half22float2(*reinterpret_cast<__half2*>(&v.y));
        a0 += f0.x; a1 += f0.y; a2 += f1.x; a3 += f1.y;
    }
    float di = g_deginv[node];
    __half2 o0 = __floats2half2_rn(a0 * di, a1 * di);
    __half2 o1 = __floats2half2_rn(a2 * di, a3 * di);
    reinterpret_cast<uint2*>(outmean)[(size_t)node * 32 + lane] =
        make_uint2(*(uint32_t*)&o0, *(uint32_t*)&o1);
}

// ====== fp16 GEMM: B fully resident in smem, A double-buffered + prefetched ======
__device__ __forceinline__ uint32_t smem_u32(const void* p) {
    uint32_t a;
    asm("{ .reg .u64 t; cvta.to.shared.u64 t, %1; cvt.u32.u64 %0, t; }" : "=r"(a) : "l"(p));
    return a;
}
__device__ __forceinline__ void ldsm_x4(uint32_t& r0, uint32_t& r1, uint32_t& r2, uint32_t& r3, uint32_t a) {
    asm volatile("ldmatrix.sync.aligned.m8n8.x4.shared.b16 {%0,%1,%2,%3}, [%4];"
                 : "=r"(r0), "=r"(r1), "=r"(r2), "=r"(r3) : "r"(a));
}
__device__ __forceinline__ void ldsm_x4_t(uint32_t& r0, uint32_t& r1, uint32_t& r2, uint32_t& r3, uint32_t a) {
    asm volatile("ldmatrix.sync.aligned.m8n8.x4.trans.shared.b16 {%0,%1,%2,%3}, [%4];"
                 : "=r"(r0), "=r"(r1), "=r"(r2), "=r"(r3) : "r"(a));
}
__device__ __forceinline__ void mma_fp16(float* c, uint32_t a0, uint32_t a1, uint32_t a2, uint32_t a3,
                                         uint32_t b0, uint32_t b1) {
    asm volatile("mma.sync.aligned.m16n8k16.row.col.f32.f16.f16.f32 "
                 "{%0,%1,%2,%3}, {%4,%5,%6,%7}, {%8,%9}, {%0,%1,%2,%3};"
                 : "+f"(c[0]), "+f"(c[1]), "+f"(c[2]), "+f"(c[3])
                 : "r"(a0), "r"(a1), "r"(a2), "r"(a3), "r"(b0), "r"(b1));
}
__device__ __forceinline__ uint32_t pack_h2(float x, float y) {
    __half2 t = __floats2half2_rn(x, y);
    return *reinterpret_cast<uint32_t*>(&t);
}

#define APAD 40
#define BPAD 136
#define OFF_A 0              // 2 A buffers: 2 * 128*APAD*2 = 20480
#define ABUF  10240
#define OFF_B 20480          // B resident: 256*BPAD*2 = 69632
#define GSMEM 90112

// mode 1: relu, write fp16 to outh. mode 0: write fp32 to outf.
__global__ __launch_bounds__(256, 2) void gemm_mma_kernel(
    const __half* __restrict__ A1, const __half* __restrict__ A2,
    const __half* __restrict__ Wh,   // [256 k][128 n] fp16
    const float* __restrict__ bias,
    float* __restrict__ outf, __half* __restrict__ outh, int mode)
{
    extern __shared__ char smem[];
    int tid = threadIdx.x, lane = tid & 31, wid = tid >> 5;
    int warp_m = wid & 3;
    int warp_n = wid >> 2;
    int m0 = blockIdx.x * 128;
    uint32_t sb = smem_u32(smem);

    float acc[2][8][4];
    #pragma unroll
    for (int i = 0; i < 2; ++i)
        #pragma unroll
        for (int j = 0; j < 8; ++j)
            #pragma unroll
            for (int q = 0; q < 4; ++q) acc[i][j][q] = 0.f;

    int a_lrow = lane & 15;
    int a_lcol = (lane >> 4) << 3;
    int b_lk   = lane & 15;
    int b_ln   = (lane >> 4) << 3;

    // ---- prologue: all of B (256 k-rows) + A chunk 0 ----
    {
        char* base = smem;
        #pragma unroll
        for (int i = 0; i < 16; ++i) {       // 4096 uint4 groups: 256 rows x 16
            int u = tid + i * 256;
            int kr = u >> 4, n8 = (u & 15) * 8;
            uint4 v = __ldg(reinterpret_cast<const uint4*>(Wh + (size_t)kr * DD + n8));
            *reinterpret_cast<uint4*>(base + OFF_B + (uint32_t)(kr * BPAD + n8) * 2) = v;
        }
        #pragma unroll
        for (int i = 0; i < 4; ++i) {
            int f = tid + i * 256;
            int row = f >> 3, c4 = (f & 7) * 4;
            int gm = m0 + row;
            uint2 v = (gm < NN) ? __ldg(reinterpret_cast<const uint2*>(A1 + (size_t)gm * DD + c4))
                                : make_uint2(0u, 0u);
            *reinterpret_cast<uint2*>(base + OFF_A + (uint32_t)(row * APAD + c4) * 2) = v;
        }
    }
    __syncthreads();

    for (int ch = 0; ch < 8; ++ch) {
        // ---- prefetch next chunk's A into registers ----
        uint2 av2[4];
        if (ch < 7) {
            const __half* Abase = (ch + 1 < 4) ? A1 : A2;
            int cb = ((ch + 1) & 3) * 32;
            #pragma unroll
            for (int i = 0; i < 4; ++i) {
                int f = tid + i * 256;
                int row = f >> 3, c4 = (f & 7) * 4;
                int gm = m0 + row;
                av2[i] = (gm < NN) ? __ldg(reinterpret_cast<const uint2*>(Abase + (size_t)gm * DD + cb + c4))
                                   : make_uint2(0u, 0u);
            }
        }

        // ---- compute from A buffer ch&1, resident B ----
        uint32_t a_b = sb + OFF_A + (uint32_t)(ch & 1) * ABUF;
        uint32_t b_b = sb + OFF_B;

        #pragma unroll
        for (int ks = 0; ks < 2; ++ks) {
            uint32_t a[2][4];
            #pragma unroll
            for (int mt = 0; mt < 2; ++mt) {
                int row = warp_m * 32 + mt * 16 + a_lrow;
                int col = ks * 16 + a_lcol;
                ldsm_x4(a[mt][0], a[mt][1], a[mt][2], a[mt][3],
                        a_b + (uint32_t)(row * APAD + col) * 2);
            }
            #pragma unroll
            for (int ng = 0; ng < 4; ++ng) {
                int kk = ch * 32 + ks * 16 + b_lk;
                int nn = warp_n * 64 + ng * 16 + b_ln;
                uint32_t b0, b1, b2, b3;
                ldsm_x4_t(b0, b1, b2, b3, b_b + (uint32_t)(kk * BPAD + nn) * 2);
                #pragma unroll
                for (int mt = 0; mt < 2; ++mt) {
                    mma_fp16(acc[mt][ng * 2 + 0], a[mt][0], a[mt][1], a[mt][2], a[mt][3], b0, b1);
                    mma_fp16(acc[mt][ng * 2 + 1], a[mt][0], a[mt][1], a[mt][2], a[mt][3], b2, b3);
                }
            }
        }

        // ---- store next A chunk into other buffer ----
        if (ch < 7) {
            char* base = smem + OFF_A + ((ch + 1) & 1) * ABUF;
            #pragma unroll
            for (int i = 0; i < 4; ++i) {
                int f = tid + i * 256;
                int row = f >> 3, c4 = (f & 7) * 4;
                *reinterpret_cast<uint2*>(base + (uint32_t)(row * APAD + c4) * 2) = av2[i];
            }
            __syncthreads();
        }
    }

    // --- epilogue ---
    int crow = lane >> 2;
    int ccol = (lane & 3) * 2;
    #pragma unroll
    for (int mt = 0; mt < 2; ++mt) {
        #pragma unroll
        for (int nt = 0; nt < 8; ++nt) {
            int col = warp_n * 64 + nt * 8 + ccol;
            float2 bb = __ldg(reinterpret_cast<const float2*>(bias + col));
            #pragma unroll
            for (int h = 0; h < 2; ++h) {
                int row = m0 + warp_m * 32 + mt * 16 + crow + h * 8;
                if (row >= NN) continue;
                float lo = acc[mt][nt][h * 2 + 0] + bb.x;
                float hi = acc[mt][nt][h * 2 + 1] + bb.y;
                if (mode == 1) {
                    lo = fmaxf(lo, 0.f); hi = fmaxf(hi, 0.f);
                    *reinterpret_cast<uint32_t*>(outh + (size_t)row * DD + col) = pack_h2(lo, hi);
                } else {
                    *reinterpret_cast<float2*>(outf + (size_t)row * DD + col) = make_float2(lo, hi);
                }
            }
        }
    }
}

// ---------------- launch ----------------
extern "C" void kernel_launch(void* const* d_in, const int* in_sizes, int n_in,
                              void* d_out, int out_size) {
    const float* in_feat  = (const float*)d_in[0];
    const float* W1_self  = (const float*)d_in[1];
    const float* W1_neigh = (const float*)d_in[2];
    const float* b1       = (const float*)d_in[3];
    const float* W2_self  = (const float*)d_in[4];
    const float* W2_neigh = (const float*)d_in[5];
    const float* b2       = (const float*)d_in[6];
    const int*   src      = (const int*)d_in[7];
    const int*   dst      = (const int*)d_in[8];
    float* out = (float*)d_out;

    int* counts_p;
    __half *xh_p, *mh_p, *hh_p, *wh_p;
    cudaGetSymbolAddress((void**)&counts_p, g_counts);
    cudaGetSymbolAddress((void**)&xh_p, g_xh);
    cudaGetSymbolAddress((void**)&mh_p, g_mh);
    cudaGetSymbolAddress((void**)&hh_p, g_hh);
    cudaGetSymbolAddress((void**)&wh_p, g_wh);

    cudaFuncSetAttribute(gemm_mma_kernel, cudaFuncAttributeMaxDynamicSharedMemorySize, GSMEM);

    cudaMemsetAsync(counts_p, 0, NN * sizeof(int));

    int conv_blocks = (NN * DD / 4 + 255) / 256;
    hist_fused_kernel<<<HB + conv_blocks, 256>>>(dst, in_feat);
    scan_local_kernel<<<NB, 1024>>>();
    finalize_kernel<<<(NN + 255) / 256, 256>>>();
    scatter_fused_kernel<<<SC_BLOCKS + 64, 256>>>(src, dst,
        W1_self, W1_neigh, W2_self, W2_neigh);

    int agg_grid  = (NN + 7) / 8;
    int gemm_grid = (NN + 127) / 128;

    // layer 1
    agg_kernel<<<agg_grid, 256>>>(xh_p, mh_p);
    gemm_mma_kernel<<<gemm_grid, 256, GSMEM>>>(xh_p, mh_p, wh_p, b1, nullptr, hh_p, 1);
    // layer 2
    agg_kernel<<<agg_grid, 256>>>(hh_p, mh_p);
    gemm_mma_kernel<<<gemm_grid, 256, GSMEM>>>(hh_p, mh_p, wh_p + 256 * DD, b2, out, nullptr, 0);
}